// round 5
// baseline (speedup 1.0000x reference)
#include <cuda_runtime.h>

#define KBINS 10000
#define MAXN  8400000
#define NB    148          // one chunk-block per SM
#define NT    1024
#define SCAN_ITEMS 10      // 1024 * 10 >= KBINS

// ------------------------- static device scratch (no allocs) ----------------
__device__ __align__(16) float          g_expg2[MAXN];  // exp(lh) at desc pos pd
__device__ __align__(16) int            g_pasc[MAXN];   // pasc[j] = original index of asc-rank-j elem
__device__ __align__(16) unsigned short g_jbin[MAXN];   // bin of asc position j (== sdur[j])
__device__ __align__(16) unsigned char  g_e2u8[MAXN];   // event at desc pos pd
__device__ int   g_H[NB * KBINS];     // per-block histograms
__device__ int   g_O[NB * KBINS];     // per-block per-bin global start offsets
__device__ int   g_C[KBINS];          // total counts
__device__ int   g_off[KBINS];        // N - 2*S[k] - C[k]  (pd = j + off)
__device__ float g_expg_sum[KBINS];
__device__ float g_ev_sum[KBINS];
__device__ float g_base[KBINS];
__device__ float g_totE;
__device__ double g_mse;

// ------------------------- kernels ------------------------------------------
__global__ void k_zero() {
    int i = blockIdx.x * blockDim.x + threadIdx.x;
    if (i < KBINS) { g_C[i] = 0; g_expg_sum[i] = 0.f; g_ev_sum[i] = 0.f; }
}

// per-block histogram over contiguous chunk + global totals
__global__ void k_hist(const int* __restrict__ dur, int N, int CH) {
    __shared__ int sh[KBINS];
    for (int k = threadIdx.x; k < KBINS; k += NT) sh[k] = 0;
    __syncthreads();
    int b = blockIdx.x;
    int start = b * CH, end = min(start + CH, N);
    for (int i = start + threadIdx.x; i < end; i += NT) atomicAdd(&sh[dur[i]], 1);
    __syncthreads();
    for (int k = threadIdx.x; k < KBINS; k += NT) {
        int c = sh[k];
        g_H[b * KBINS + k] = c;
        if (c) atomicAdd(&g_C[k], c);
    }
}

// exclusive scan of C -> S; off[k] = N - 2S - C. (single block)
__global__ void k_scanC(int N) {
    __shared__ int s[NT];
    int tid = threadIdx.x;
    int loc[SCAN_ITEMS];
    int run = 0;
#pragma unroll
    for (int i = 0; i < SCAN_ITEMS; i++) {
        int k = tid * SCAN_ITEMS + i;
        int c = (k < KBINS) ? g_C[k] : 0;
        loc[i] = run;
        run += c;
    }
    s[tid] = run;
    __syncthreads();
    for (int o = 1; o < NT; o <<= 1) {
        int v = (tid >= o) ? s[tid - o] : 0;
        __syncthreads();
        s[tid] += v;
        __syncthreads();
    }
    int excl = tid ? s[tid - 1] : 0;
#pragma unroll
    for (int i = 0; i < SCAN_ITEMS; i++) {
        int k = tid * SCAN_ITEMS + i;
        if (k < KBINS) {
            int S = excl + loc[i];
            g_off[k] = N - 2 * S - g_C[k];
            g_C[k]   = S;   // repurpose: g_C now holds S[k] for k_blockoff
        }
    }
}

// O[b][k] = S[k] + sum_{b'<b} H[b'][k]   (coalesced across k)
__global__ void k_blockoff() {
    int k = blockIdx.x * blockDim.x + threadIdx.x;
    if (k >= KBINS) return;
    int run = g_C[k];   // = S[k]
#pragma unroll 4
    for (int b = 0; b < NB; b++) {
        g_O[b * KBINS + k] = run;
        run += g_H[b * KBINS + k];
    }
}

// Fused stable-rank + scatter + segment-sum. One block per chunk.
__global__ void __launch_bounds__(NT, 1)
k_fused(const int* __restrict__ dur, const float* __restrict__ lh,
        const int* __restrict__ ev, int N, int CH) {
    extern __shared__ char smraw[];
    int*   s_cnt  = (int*)smraw;                    // running asc positions
    float* s_segF = (float*)(smraw + KBINS * 4);    // expg sums per bin
    int*   s_segE = (int*)(smraw + KBINS * 8);      // event counts per bin
    int*   s_off  = (int*)(smraw + KBINS * 12);     // N-2S-C per bin
    int tid = threadIdx.x, wid = tid >> 5, lane = tid & 31;
    unsigned lt = (1u << lane) - 1u;
    int b = blockIdx.x;
    for (int k = tid; k < KBINS; k += NT) {
        s_cnt[k]  = g_O[b * KBINS + k];
        s_segF[k] = 0.f;
        s_segE[k] = 0;
        s_off[k]  = g_off[k];
    }
    __syncthreads();

    int start = b * CH, end = min(start + CH, N);
    for (int t0 = start; t0 < end; t0 += NT) {
        int i = t0 + tid;
        bool valid = (i < end);
        int   key = valid ? dur[i] : 0x7fffffff;
        float lhv = valid ? lh[i]  : 0.f;
        int   evv = valid ? (ev[i] & 1) : 0;

        int j = 0;
        // warp-serialized stable ranking (index order preserved)
        for (int w2 = 0; w2 < NT / 32; w2++) {
            if (wid == w2) {
                unsigned mask = __match_any_sync(0xffffffffu, key);
                int r = __popc(mask & lt);
                int base = 0;
                if (valid) base = s_cnt[key];
                __syncwarp();
                if (valid && r == 0) s_cnt[key] = base + __popc(mask);
                j = base + r;
            }
            __syncthreads();
        }

        if (valid) {
            int pd = j + s_off[key];
            float x = __expf(lhv);
            g_expg2[pd] = x;
            g_e2u8[pd]  = (unsigned char)evv;
            g_pasc[j]   = i;
            g_jbin[j]   = (unsigned short)key;
            int kk = __ldg(dur + pd);
            atomicAdd(&s_segF[kk], x);
            if (evv) atomicAdd(&s_segE[kk], 1);
        }
    }
    __syncthreads();
    for (int k = tid; k < KBINS; k += NT) {
        float a = s_segF[k]; int c = s_segE[k];
        if (a != 0.f) atomicAdd(&g_expg_sum[k], a);
        if (c)        atomicAdd(&g_ev_sum[k], (float)c);
    }
}

// base[k] = ev_sum[k] / risk[k] (reverse-cumsum risk); also totE, reset mse
__global__ void k_base() {
    __shared__ float s[NT];
    __shared__ float s2[32];
    int tid = threadIdx.x;
    float loc[SCAN_ITEMS];
    float run = 0.f, evt = 0.f;
#pragma unroll
    for (int i = 0; i < SCAN_ITEMS; i++) {
        int m = tid * SCAN_ITEMS + i;
        int k = KBINS - 1 - m;
        float v = (k >= 0) ? g_expg_sum[k] : 0.f;
        if (k >= 0) evt += g_ev_sum[k];
        run += v;
        loc[i] = run;
    }
    s[tid] = run;
    __syncthreads();
    for (int o = 1; o < NT; o <<= 1) {
        float v = (tid >= o) ? s[tid - o] : 0.f;
        __syncthreads();
        s[tid] += v;
        __syncthreads();
    }
    float excl = tid ? s[tid - 1] : 0.f;
#pragma unroll
    for (int i = 0; i < SCAN_ITEMS; i++) {
        int m = tid * SCAN_ITEMS + i;
        int k = KBINS - 1 - m;
        if (k >= 0) {
            float risk = excl + loc[i];
            g_base[k] = (risk > 0.f) ? (g_ev_sum[k] / risk) : 0.f;
        }
    }
    for (int o = 16; o; o >>= 1) evt += __shfl_down_sync(0xffffffffu, evt, o);
    if ((tid & 31) == 0) s2[tid >> 5] = evt;
    __syncthreads();
    if (tid < 32) {
        float v = s2[tid];
        for (int o = 16; o; o >>= 1) v += __shfl_down_sync(0xffffffffu, v, o);
        if (tid == 0) { g_totE = v; g_mse = 0.0; }
    }
}

// sum x^2 - 2xe with x = base[jbin[j]] * expg2[j], e = e2u8[pasc[j]]
__global__ void k_mse(int N) {
    double acc = 0.0;
    int stride = gridDim.x * blockDim.x;
    int Nv = N >> 2;
    for (int g = blockIdx.x * blockDim.x + threadIdx.x; g < Nv; g += stride) {
        int j = g * 4;
        ushort4 kb = *reinterpret_cast<const ushort4*>(g_jbin + j);
        int4 a = *reinterpret_cast<const int4*>(g_pasc + j);
        float4 xg = *reinterpret_cast<const float4*>(g_expg2 + j);
        float x0 = g_base[kb.x] * xg.x;
        float x1 = g_base[kb.y] * xg.y;
        float x2 = g_base[kb.z] * xg.z;
        float x3 = g_base[kb.w] * xg.w;
        float e0 = (float)__ldg(g_e2u8 + a.x);
        float e1 = (float)__ldg(g_e2u8 + a.y);
        float e2 = (float)__ldg(g_e2u8 + a.z);
        float e3 = (float)__ldg(g_e2u8 + a.w);
        float sv = x0 * (x0 - 2.f * e0) + x1 * (x1 - 2.f * e1)
                 + x2 * (x2 - 2.f * e2) + x3 * (x3 - 2.f * e3);
        acc += (double)sv;
    }
    if (blockIdx.x == 0 && threadIdx.x < (N & 3)) {
        int t = (N & ~3) + threadIdx.x;
        float x = g_base[g_jbin[t]] * g_expg2[t];
        float e = (float)g_e2u8[g_pasc[t]];
        acc += (double)(x * (x - 2.f * e));
    }
    __shared__ double sd[32];
    for (int o = 16; o; o >>= 1) acc += __shfl_down_sync(0xffffffffu, acc, o);
    if ((threadIdx.x & 31) == 0) sd[threadIdx.x >> 5] = acc;
    __syncthreads();
    if (threadIdx.x < 32) {
        int nw = blockDim.x >> 5;
        double v = (threadIdx.x < nw) ? sd[threadIdx.x] : 0.0;
        for (int o = 16; o; o >>= 1) v += __shfl_down_sync(0xffffffffu, v, o);
        if (threadIdx.x == 0) atomicAdd(&g_mse, v);
    }
}

__global__ void k_fin(float* out, int N) {
    double mse = (g_mse + (double)g_totE) / (double)N;
    out[0] = (g_totE == 0.f) ? 0.f : (float)mse;
}

// ------------------------- host launcher ------------------------------------
extern "C" void kernel_launch(void* const* d_in, const int* in_sizes, int n_in,
                              void* d_out, int out_size) {
    const float* lh  = (const float*)d_in[0];
    const int*   dur = (const int*)d_in[1];
    const int*   ev  = (const int*)d_in[2];
    int N = in_sizes[0];
    float* out = (float*)d_out;
    int CH = (N + NB - 1) / NB;

    size_t fused_smem = (size_t)KBINS * 16;  // cnt + segF + segE + off
    cudaFuncSetAttribute(k_fused, cudaFuncAttributeMaxDynamicSharedMemorySize,
                         (int)fused_smem);

    k_zero<<<(KBINS + NT - 1) / NT, NT>>>();
    k_hist<<<NB, NT>>>(dur, N, CH);
    k_scanC<<<1, NT>>>(N);
    k_blockoff<<<(KBINS + NT - 1) / NT, NT>>>();
    k_fused<<<NB, NT, fused_smem>>>(dur, lh, ev, N, CH);
    k_base<<<1, NT>>>();
    k_mse<<<1184, 256>>>(N);
    k_fin<<<1, 1>>>(out, N);
}

// round 6
// speedup vs baseline: 2.2315x; 2.2315x over previous
#include <cuda_runtime.h>

#define KBINS 10000
#define MAXN  8400000
#define NB    592          // ranking chunks (4 blocks/SM)
#define FNT   256          // fused threads (8 warps)
#define EPT   4            // match rounds per warp turn (128 elems/turn)
#define FTILE (FNT * EPT)  // 1024 elements per block-tile
#define HNT   512
#define SCAN_ITEMS 10      // 1024 * 10 >= KBINS

// ------------------------- static device scratch (no allocs) ----------------
__device__ __align__(16) unsigned int g_expg2[MAXN]; // packed (exp(lh), ev-bit) at desc pos
__device__ __align__(16) int          g_jasc[MAXN];  // jasc[i] = global asc rank of element i
__device__ int   g_H[NB * KBINS];    // per-block histograms
__device__ int   g_O[NB * KBINS];    // per-block per-bin global asc start offsets
__device__ int   g_C[KBINS];         // total counts
__device__ int   g_Sarr[KBINS];      // exclusive prefix S[k]
__device__ int   g_off[KBINS];       // N - 2S - C   (pd = j + off)
__device__ float g_expg_sum[KBINS];
__device__ float g_ev_sum[KBINS];
__device__ float g_base[KBINS];
__device__ float g_totE;
__device__ double g_mse;

// ------------------------- kernels ------------------------------------------
__global__ void k_zero() {
    int i = blockIdx.x * blockDim.x + threadIdx.x;
    if (i < KBINS) { g_C[i] = 0; g_expg_sum[i] = 0.f; g_ev_sum[i] = 0.f; }
}

// per-block histogram over contiguous chunk
__global__ void k_hist(const int* __restrict__ dur, int N, int CH) {
    __shared__ int sh[KBINS];
    for (int k = threadIdx.x; k < KBINS; k += HNT) sh[k] = 0;
    __syncthreads();
    int b = blockIdx.x;
    int start = b * CH, end = min(start + CH, N);
    for (int i = start + threadIdx.x; i < end; i += HNT) atomicAdd(&sh[dur[i]], 1);
    __syncthreads();
    for (int k = threadIdx.x; k < KBINS; k += HNT) {
        int c = sh[k];
        g_H[b * KBINS + k] = c;
        if (c) atomicAdd(&g_C[k], c);
    }
}

// exclusive scan of C -> S; off = N - 2S - C  (single block)
__global__ void k_scanC(int N) {
    __shared__ int s[1024];
    int tid = threadIdx.x;
    int loc[SCAN_ITEMS];
    int run = 0;
#pragma unroll
    for (int i = 0; i < SCAN_ITEMS; i++) {
        int k = tid * SCAN_ITEMS + i;
        int c = (k < KBINS) ? g_C[k] : 0;
        loc[i] = run;
        run += c;
    }
    s[tid] = run;
    __syncthreads();
    for (int o = 1; o < 1024; o <<= 1) {
        int v = (tid >= o) ? s[tid - o] : 0;
        __syncthreads();
        s[tid] += v;
        __syncthreads();
    }
    int excl = tid ? s[tid - 1] : 0;
#pragma unroll
    for (int i = 0; i < SCAN_ITEMS; i++) {
        int k = tid * SCAN_ITEMS + i;
        if (k < KBINS) {
            int S = excl + loc[i];
            g_Sarr[k] = S;
            g_off[k]  = N - 2 * S - g_C[k];
        }
    }
}

// O[b][k] = S[k] + sum_{b'<b} H[b'][k]; one thread per k, unrolled for MLP
__global__ void k_blockoff() {
    int k = blockIdx.x * blockDim.x + threadIdx.x;
    if (k >= KBINS) return;
    int run = g_Sarr[k];
#pragma unroll 8
    for (int b = 0; b < NB; b++) {
        g_O[b * KBINS + k] = run;
        run += g_H[b * KBINS + k];
    }
}

// Fused stable-rank + scatter. Warps hand off a per-block smem ticket so the
// serialized per-key ranking runs with NO block barriers; everything heavy
// (loads, expf) happens outside the critical section.
__global__ void __launch_bounds__(FNT, 4)
k_fused(const int* __restrict__ dur, const float* __restrict__ lh,
        const int* __restrict__ ev, int N, int CH) {
    __shared__ int s_cnt[KBINS + 1];   // running global asc positions (+ sentinel)
    __shared__ int s_flag;
    int tid = threadIdx.x, wid = tid >> 5, lane = tid & 31;
    unsigned lt = (1u << lane) - 1u;
    int b = blockIdx.x;
    for (int k = tid; k < KBINS; k += FNT) s_cnt[k] = g_O[b * KBINS + k];
    if (tid == 0) { s_cnt[KBINS] = 0; s_flag = 0; }
    __syncthreads();

    int start = b * CH, end = min(start + CH, N);
    int ticket = 0;
    for (int t0 = start; t0 < end; t0 += FTILE, ticket += 8) {
        int key[EPT]; unsigned px[EPT]; int idx0 = t0 + wid * (EPT * 32) + lane;
        // ---- prefetch + compute outside critical section ----
#pragma unroll
        for (int m = 0; m < EPT; m++) {
            int i = idx0 + m * 32;
            bool v = (i < end);
            key[m] = v ? dur[i] : KBINS;
            float lhv = v ? lh[i] : 0.f;
            int evv = v ? (ev[i] & 1) : 0;
            px[m] = (__float_as_uint(__expf(lhv)) & 0xFFFFFFFEu) | (unsigned)evv;
        }
        // ---- wait for our turn ----
        int target = ticket + wid;
        while (*(volatile int*)&s_flag != target) {}
        __threadfence_block();
        // ---- serialized ranking (smem only) ----
        int j[EPT];
#pragma unroll
        for (int m = 0; m < EPT; m++) {
            unsigned mask = __match_any_sync(0xffffffffu, key[m]);
            int r = __popc(mask & lt);
            int base = s_cnt[key[m]];
            __syncwarp();
            if (r == 0) s_cnt[key[m]] = base + __popc(mask);
            __syncwarp();
            j[m] = base + r;
        }
        __threadfence_block();
        if (lane == 0) *(volatile int*)&s_flag = target + 1;
        // ---- writes outside critical section ----
#pragma unroll
        for (int m = 0; m < EPT; m++) {
            if (key[m] < KBINS) {
                int i = idx0 + m * 32;
                int pd = j[m] + __ldg(g_off + key[m]);
                g_expg2[pd] = px[m];
                g_jasc[i]   = j[m];
            }
        }
    }
}

// linear segment sums: expg_sum[dur[p]] += exp-part(expg2[p]); ev_sum += bit
__global__ void k_segsum(const int* __restrict__ dur, int N) {
    extern __shared__ char smraw[];
    float* sE = (float*)smraw;
    int*   sV = (int*)(smraw + KBINS * 4);
    for (int k = threadIdx.x; k < KBINS; k += blockDim.x) { sE[k] = 0.f; sV[k] = 0; }
    __syncthreads();
    int stride = gridDim.x * blockDim.x;
    int Nv = N >> 2;
    for (int g = blockIdx.x * blockDim.x + threadIdx.x; g < Nv; g += stride) {
        int p = g * 4;
        int4 k4 = *reinterpret_cast<const int4*>(dur + p);
        uint4 x4 = *reinterpret_cast<const uint4*>(g_expg2 + p);
        atomicAdd(&sE[k4.x], __uint_as_float(x4.x & 0xFFFFFFFEu));
        atomicAdd(&sE[k4.y], __uint_as_float(x4.y & 0xFFFFFFFEu));
        atomicAdd(&sE[k4.z], __uint_as_float(x4.z & 0xFFFFFFFEu));
        atomicAdd(&sE[k4.w], __uint_as_float(x4.w & 0xFFFFFFFEu));
        if (x4.x & 1u) atomicAdd(&sV[k4.x], 1);
        if (x4.y & 1u) atomicAdd(&sV[k4.y], 1);
        if (x4.z & 1u) atomicAdd(&sV[k4.z], 1);
        if (x4.w & 1u) atomicAdd(&sV[k4.w], 1);
    }
    if (blockIdx.x == 0 && threadIdx.x < (N & 3)) {
        int p = (N & ~3) + threadIdx.x;
        int k = dur[p];
        unsigned x = g_expg2[p];
        atomicAdd(&sE[k], __uint_as_float(x & 0xFFFFFFFEu));
        if (x & 1u) atomicAdd(&sV[k], 1);
    }
    __syncthreads();
    for (int k = threadIdx.x; k < KBINS; k += blockDim.x) {
        float a = sE[k]; int c = sV[k];
        if (a != 0.f) atomicAdd(&g_expg_sum[k], a);
        if (c)        atomicAdd(&g_ev_sum[k], (float)c);
    }
}

// base[k] = ev_sum / reverse-cumsum(expg_sum); totE; reset mse
__global__ void k_base() {
    __shared__ float s[1024];
    __shared__ float s2[32];
    int tid = threadIdx.x;
    float loc[SCAN_ITEMS];
    float run = 0.f, evt = 0.f;
#pragma unroll
    for (int i = 0; i < SCAN_ITEMS; i++) {
        int m = tid * SCAN_ITEMS + i;
        int k = KBINS - 1 - m;
        float v = (k >= 0) ? g_expg_sum[k] : 0.f;
        if (k >= 0) evt += g_ev_sum[k];
        run += v;
        loc[i] = run;
    }
    s[tid] = run;
    __syncthreads();
    for (int o = 1; o < 1024; o <<= 1) {
        float v = (tid >= o) ? s[tid - o] : 0.f;
        __syncthreads();
        s[tid] += v;
        __syncthreads();
    }
    float excl = tid ? s[tid - 1] : 0.f;
#pragma unroll
    for (int i = 0; i < SCAN_ITEMS; i++) {
        int m = tid * SCAN_ITEMS + i;
        int k = KBINS - 1 - m;
        if (k >= 0) {
            float risk = excl + loc[i];
            g_base[k] = (risk > 0.f) ? (g_ev_sum[k] / risk) : 0.f;
        }
    }
    for (int o = 16; o; o >>= 1) evt += __shfl_down_sync(0xffffffffu, evt, o);
    if ((tid & 31) == 0) s2[tid >> 5] = evt;
    __syncthreads();
    if (tid < 32) {
        float v = s2[tid];
        for (int o = 16; o; o >>= 1) v += __shfl_down_sync(0xffffffffu, v, o);
        if (tid == 0) { g_totE = v; g_mse = 0.0; }
    }
}

// per original element i: term = (base[dur[i]] * exp(expg2[jasc[i]]) - ebit(expg2[i]))^2
__global__ void k_mse(const int* __restrict__ dur, int N) {
    double acc = 0.0;
    int stride = gridDim.x * blockDim.x;
    int Nv = N >> 2;
    for (int g = blockIdx.x * blockDim.x + threadIdx.x; g < Nv; g += stride) {
        int i = g * 4;
        int4  k4 = *reinterpret_cast<const int4*>(dur + i);
        int4  j4 = *reinterpret_cast<const int4*>(g_jasc + i);
        uint4 p4 = *reinterpret_cast<const uint4*>(g_expg2 + i);
        unsigned q0 = __ldg(g_expg2 + j4.x), q1 = __ldg(g_expg2 + j4.y);
        unsigned q2 = __ldg(g_expg2 + j4.z), q3 = __ldg(g_expg2 + j4.w);
        float t0 = g_base[k4.x] * __uint_as_float(q0 & 0xFFFFFFFEu) - (float)(p4.x & 1u);
        float t1 = g_base[k4.y] * __uint_as_float(q1 & 0xFFFFFFFEu) - (float)(p4.y & 1u);
        float t2 = g_base[k4.z] * __uint_as_float(q2 & 0xFFFFFFFEu) - (float)(p4.z & 1u);
        float t3 = g_base[k4.w] * __uint_as_float(q3 & 0xFFFFFFFEu) - (float)(p4.w & 1u);
        acc += (double)(t0 * t0 + t1 * t1 + t2 * t2 + t3 * t3);
    }
    if (blockIdx.x == 0 && threadIdx.x < (N & 3)) {
        int i = (N & ~3) + threadIdx.x;
        unsigned q = g_expg2[g_jasc[i]];
        float t = g_base[dur[i]] * __uint_as_float(q & 0xFFFFFFFEu)
                - (float)(g_expg2[i] & 1u);
        acc += (double)(t * t);
    }
    __shared__ double sd[32];
    for (int o = 16; o; o >>= 1) acc += __shfl_down_sync(0xffffffffu, acc, o);
    if ((threadIdx.x & 31) == 0) sd[threadIdx.x >> 5] = acc;
    __syncthreads();
    if (threadIdx.x < 32) {
        int nw = blockDim.x >> 5;
        double v = (threadIdx.x < nw) ? sd[threadIdx.x] : 0.0;
        for (int o = 16; o; o >>= 1) v += __shfl_down_sync(0xffffffffu, v, o);
        if (threadIdx.x == 0) atomicAdd(&g_mse, v);
    }
}

__global__ void k_fin(float* out, int N) {
    out[0] = (g_totE == 0.f) ? 0.f : (float)(g_mse / (double)N);
}

// ------------------------- host launcher ------------------------------------
extern "C" void kernel_launch(void* const* d_in, const int* in_sizes, int n_in,
                              void* d_out, int out_size) {
    const float* lh  = (const float*)d_in[0];
    const int*   dur = (const int*)d_in[1];
    const int*   ev  = (const int*)d_in[2];
    int N = in_sizes[0];
    float* out = (float*)d_out;
    int CH = (N + NB - 1) / NB;

    size_t seg_smem = (size_t)KBINS * 8;
    cudaFuncSetAttribute(k_segsum, cudaFuncAttributeMaxDynamicSharedMemorySize,
                         (int)seg_smem);

    k_zero<<<(KBINS + 1023) / 1024, 1024>>>();
    k_hist<<<NB, HNT>>>(dur, N, CH);
    k_scanC<<<1, 1024>>>(N);
    k_blockoff<<<(KBINS + 127) / 128, 128>>>();
    k_fused<<<NB, FNT>>>(dur, lh, ev, N, CH);
    k_segsum<<<148, 1024, seg_smem>>>(dur, N);
    k_base<<<1, 1024>>>();
    k_mse<<<1184, 256>>>(dur, N);
    k_fin<<<1, 1>>>(out, N);
}

// round 7
// speedup vs baseline: 2.9336x; 1.3146x over previous
#include <cuda_runtime.h>

#define KBINS 10000
#define MAXN  8400000
#define NB    296          // ranking chunks (2 blocks/SM)
#define FNT   256          // fused threads (8 warps)
#define EPT   4            // match rounds per warp turn (128 elems/turn)
#define FTILE (FNT * EPT)  // 1024 elements per block-tile
#define HNT   512
#define SCAN_ITEMS 10      // 1024 * 10 >= KBINS

// ------------------------- static device scratch (no allocs) ----------------
__device__ __align__(16) unsigned int g_expg2[MAXN]; // packed (exp(lh), ev-bit) at desc pos
__device__ __align__(16) int          g_jasc[MAXN];  // jasc[i] = global asc rank of element i
__device__ int   g_H[NB * KBINS];    // per-block histograms
__device__ int   g_O[NB * KBINS];    // per-block per-bin global asc start offsets
__device__ int   g_C[KBINS];         // total counts
__device__ int   g_Sarr[KBINS];      // exclusive prefix S[k]
__device__ int   g_off[KBINS];       // N - 2S - C   (pd = j + off)
__device__ float g_expg_sum[KBINS];
__device__ float g_ev_sum[KBINS];
__device__ float g_base[KBINS];
__device__ float g_totE;
__device__ double g_mse;

// ------------------------- kernels ------------------------------------------
__global__ void k_zero() {
    int i = blockIdx.x * blockDim.x + threadIdx.x;
    if (i < KBINS) { g_C[i] = 0; g_expg_sum[i] = 0.f; g_ev_sum[i] = 0.f; }
}

// per-block histogram over contiguous chunk
__global__ void k_hist(const int* __restrict__ dur, int N, int CH) {
    __shared__ int sh[KBINS];
    for (int k = threadIdx.x; k < KBINS; k += HNT) sh[k] = 0;
    __syncthreads();
    int b = blockIdx.x;
    int start = b * CH, end = min(start + CH, N);
    for (int i = start + threadIdx.x; i < end; i += HNT) atomicAdd(&sh[dur[i]], 1);
    __syncthreads();
    for (int k = threadIdx.x; k < KBINS; k += HNT) {
        int c = sh[k];
        g_H[b * KBINS + k] = c;
        if (c) atomicAdd(&g_C[k], c);
    }
}

// exclusive scan of C -> S; off = N - 2S - C  (single block)
__global__ void k_scanC(int N) {
    __shared__ int s[1024];
    int tid = threadIdx.x;
    int loc[SCAN_ITEMS];
    int run = 0;
#pragma unroll
    for (int i = 0; i < SCAN_ITEMS; i++) {
        int k = tid * SCAN_ITEMS + i;
        int c = (k < KBINS) ? g_C[k] : 0;
        loc[i] = run;
        run += c;
    }
    s[tid] = run;
    __syncthreads();
    for (int o = 1; o < 1024; o <<= 1) {
        int v = (tid >= o) ? s[tid - o] : 0;
        __syncthreads();
        s[tid] += v;
        __syncthreads();
    }
    int excl = tid ? s[tid - 1] : 0;
#pragma unroll
    for (int i = 0; i < SCAN_ITEMS; i++) {
        int k = tid * SCAN_ITEMS + i;
        if (k < KBINS) {
            int S = excl + loc[i];
            g_Sarr[k] = S;
            g_off[k]  = N - 2 * S - g_C[k];
        }
    }
}

// O[b][k] = S[k] + sum_{b'<b} H[b'][k] — one WARP per bin, shfl scan over b
__global__ void k_blockoff() {
    int w = (blockIdx.x * blockDim.x + threadIdx.x) >> 5;
    int lane = threadIdx.x & 31;
    if (w >= KBINS) return;
    int k = w;
    int carry = __shfl_sync(0xffffffffu, (lane == 0) ? g_Sarr[k] : 0, 0);
#pragma unroll
    for (int t = 0; t < (NB + 31) / 32; t++) {
        int b = t * 32 + lane;
        int v = (b < NB) ? g_H[b * KBINS + k] : 0;
        int x = v;
#pragma unroll
        for (int o = 1; o < 32; o <<= 1) {
            int y = __shfl_up_sync(0xffffffffu, x, o);
            if (lane >= o) x += y;
        }
        if (b < NB) g_O[b * KBINS + k] = carry + x - v;
        carry += __shfl_sync(0xffffffffu, x, 31);
    }
}

// Fused stable-rank + scatter. Warps hand off a per-block smem ticket so the
// serialized per-key ranking runs with NO block barriers; everything heavy
// (loads, expf) happens outside the critical section.
__global__ void __launch_bounds__(FNT, 2)
k_fused(const int* __restrict__ dur, const float* __restrict__ lh,
        const int* __restrict__ ev, int N, int CH) {
    __shared__ int s_cnt[KBINS + 1];   // running global asc positions (+ sentinel)
    __shared__ int s_flag;
    int tid = threadIdx.x, wid = tid >> 5, lane = tid & 31;
    unsigned lt = (1u << lane) - 1u;
    int b = blockIdx.x;
    for (int k = tid; k < KBINS; k += FNT) s_cnt[k] = g_O[b * KBINS + k];
    if (tid == 0) { s_cnt[KBINS] = 0; s_flag = 0; }
    __syncthreads();

    int start = b * CH, end = min(start + CH, N);
    int ticket = 0;
    for (int t0 = start; t0 < end; t0 += FTILE, ticket += 8) {
        int key[EPT]; unsigned px[EPT]; int idx0 = t0 + wid * (EPT * 32) + lane;
        // ---- prefetch + compute outside critical section ----
#pragma unroll
        for (int m = 0; m < EPT; m++) {
            int i = idx0 + m * 32;
            bool v = (i < end);
            key[m] = v ? dur[i] : KBINS;
            float lhv = v ? lh[i] : 0.f;
            int evv = v ? (ev[i] & 1) : 0;
            px[m] = (__float_as_uint(__expf(lhv)) & 0xFFFFFFFEu) | (unsigned)evv;
        }
        // ---- wait for our turn ----
        int target = ticket + wid;
        while (*(volatile int*)&s_flag != target) {}
        __threadfence_block();
        // ---- serialized ranking (smem only) ----
        int j[EPT];
#pragma unroll
        for (int m = 0; m < EPT; m++) {
            unsigned mask = __match_any_sync(0xffffffffu, key[m]);
            int r = __popc(mask & lt);
            int base = s_cnt[key[m]];
            __syncwarp();
            if (r == 0) s_cnt[key[m]] = base + __popc(mask);
            __syncwarp();
            j[m] = base + r;
        }
        __threadfence_block();
        if (lane == 0) *(volatile int*)&s_flag = target + 1;
        // ---- writes outside critical section ----
#pragma unroll
        for (int m = 0; m < EPT; m++) {
            if (key[m] < KBINS) {
                int i = idx0 + m * 32;
                int pd = j[m] + __ldg(g_off + key[m]);
                g_expg2[pd] = px[m];
                g_jasc[i]   = j[m];
            }
        }
    }
}

// linear segment sums: expg_sum[dur[p]] += exp-part(expg2[p]); ev_sum += bit
__global__ void k_segsum(const int* __restrict__ dur, int N) {
    extern __shared__ char smraw[];
    float* sE = (float*)smraw;
    int*   sV = (int*)(smraw + KBINS * 4);
    for (int k = threadIdx.x; k < KBINS; k += blockDim.x) { sE[k] = 0.f; sV[k] = 0; }
    __syncthreads();
    int stride = gridDim.x * blockDim.x;
    int Nv = N >> 2;
    for (int g = blockIdx.x * blockDim.x + threadIdx.x; g < Nv; g += stride) {
        int p = g * 4;
        int4 k4 = *reinterpret_cast<const int4*>(dur + p);
        uint4 x4 = *reinterpret_cast<const uint4*>(g_expg2 + p);
        atomicAdd(&sE[k4.x], __uint_as_float(x4.x & 0xFFFFFFFEu));
        atomicAdd(&sE[k4.y], __uint_as_float(x4.y & 0xFFFFFFFEu));
        atomicAdd(&sE[k4.z], __uint_as_float(x4.z & 0xFFFFFFFEu));
        atomicAdd(&sE[k4.w], __uint_as_float(x4.w & 0xFFFFFFFEu));
        if (x4.x & 1u) atomicAdd(&sV[k4.x], 1);
        if (x4.y & 1u) atomicAdd(&sV[k4.y], 1);
        if (x4.z & 1u) atomicAdd(&sV[k4.z], 1);
        if (x4.w & 1u) atomicAdd(&sV[k4.w], 1);
    }
    if (blockIdx.x == 0 && threadIdx.x < (N & 3)) {
        int p = (N & ~3) + threadIdx.x;
        int k = dur[p];
        unsigned x = g_expg2[p];
        atomicAdd(&sE[k], __uint_as_float(x & 0xFFFFFFFEu));
        if (x & 1u) atomicAdd(&sV[k], 1);
    }
    __syncthreads();
    for (int k = threadIdx.x; k < KBINS; k += blockDim.x) {
        float a = sE[k]; int c = sV[k];
        if (a != 0.f) atomicAdd(&g_expg_sum[k], a);
        if (c)        atomicAdd(&g_ev_sum[k], (float)c);
    }
}

// base[k] = ev_sum / reverse-cumsum(expg_sum); totE; reset mse
__global__ void k_base() {
    __shared__ float s[1024];
    __shared__ float s2[32];
    int tid = threadIdx.x;
    float loc[SCAN_ITEMS];
    float run = 0.f, evt = 0.f;
#pragma unroll
    for (int i = 0; i < SCAN_ITEMS; i++) {
        int m = tid * SCAN_ITEMS + i;
        int k = KBINS - 1 - m;
        float v = (k >= 0) ? g_expg_sum[k] : 0.f;
        if (k >= 0) evt += g_ev_sum[k];
        run += v;
        loc[i] = run;
    }
    s[tid] = run;
    __syncthreads();
    for (int o = 1; o < 1024; o <<= 1) {
        float v = (tid >= o) ? s[tid - o] : 0.f;
        __syncthreads();
        s[tid] += v;
        __syncthreads();
    }
    float excl = tid ? s[tid - 1] : 0.f;
#pragma unroll
    for (int i = 0; i < SCAN_ITEMS; i++) {
        int m = tid * SCAN_ITEMS + i;
        int k = KBINS - 1 - m;
        if (k >= 0) {
            float risk = excl + loc[i];
            g_base[k] = (risk > 0.f) ? (g_ev_sum[k] / risk) : 0.f;
        }
    }
    for (int o = 16; o; o >>= 1) evt += __shfl_down_sync(0xffffffffu, evt, o);
    if ((tid & 31) == 0) s2[tid >> 5] = evt;
    __syncthreads();
    if (tid < 32) {
        float v = s2[tid];
        for (int o = 16; o; o >>= 1) v += __shfl_down_sync(0xffffffffu, v, o);
        if (tid == 0) { g_totE = v; g_mse = 0.0; }
    }
}

// per original element i: term = (base[dur[i]] * exp-part(expg2[jasc[i]]) - ebit(expg2[i]))^2
__global__ void k_mse(const int* __restrict__ dur, int N) {
    double acc = 0.0;
    int stride = gridDim.x * blockDim.x;
    int Nv = N >> 2;
    for (int g = blockIdx.x * blockDim.x + threadIdx.x; g < Nv; g += stride) {
        int i = g * 4;
        int4  k4 = *reinterpret_cast<const int4*>(dur + i);
        int4  j4 = *reinterpret_cast<const int4*>(g_jasc + i);
        uint4 p4 = *reinterpret_cast<const uint4*>(g_expg2 + i);
        unsigned q0 = __ldg(g_expg2 + j4.x), q1 = __ldg(g_expg2 + j4.y);
        unsigned q2 = __ldg(g_expg2 + j4.z), q3 = __ldg(g_expg2 + j4.w);
        float t0 = g_base[k4.x] * __uint_as_float(q0 & 0xFFFFFFFEu) - (float)(p4.x & 1u);
        float t1 = g_base[k4.y] * __uint_as_float(q1 & 0xFFFFFFFEu) - (float)(p4.y & 1u);
        float t2 = g_base[k4.z] * __uint_as_float(q2 & 0xFFFFFFFEu) - (float)(p4.z & 1u);
        float t3 = g_base[k4.w] * __uint_as_float(q3 & 0xFFFFFFFEu) - (float)(p4.w & 1u);
        acc += (double)(t0 * t0 + t1 * t1 + t2 * t2 + t3 * t3);
    }
    if (blockIdx.x == 0 && threadIdx.x < (N & 3)) {
        int i = (N & ~3) + threadIdx.x;
        unsigned q = g_expg2[g_jasc[i]];
        float t = g_base[dur[i]] * __uint_as_float(q & 0xFFFFFFFEu)
                - (float)(g_expg2[i] & 1u);
        acc += (double)(t * t);
    }
    __shared__ double sd[32];
    for (int o = 16; o; o >>= 1) acc += __shfl_down_sync(0xffffffffu, acc, o);
    if ((threadIdx.x & 31) == 0) sd[threadIdx.x >> 5] = acc;
    __syncthreads();
    if (threadIdx.x < 32) {
        int nw = blockDim.x >> 5;
        double v = (threadIdx.x < nw) ? sd[threadIdx.x] : 0.0;
        for (int o = 16; o; o >>= 1) v += __shfl_down_sync(0xffffffffu, v, o);
        if (threadIdx.x == 0) atomicAdd(&g_mse, v);
    }
}

__global__ void k_fin(float* out, int N) {
    out[0] = (g_totE == 0.f) ? 0.f : (float)(g_mse / (double)N);
}

// ------------------------- host launcher ------------------------------------
extern "C" void kernel_launch(void* const* d_in, const int* in_sizes, int n_in,
                              void* d_out, int out_size) {
    const float* lh  = (const float*)d_in[0];
    const int*   dur = (const int*)d_in[1];
    const int*   ev  = (const int*)d_in[2];
    int N = in_sizes[0];
    float* out = (float*)d_out;
    int CH = (N + NB - 1) / NB;

    size_t seg_smem = (size_t)KBINS * 8;
    cudaFuncSetAttribute(k_segsum, cudaFuncAttributeMaxDynamicSharedMemorySize,
                         (int)seg_smem);

    k_zero<<<(KBINS + 1023) / 1024, 1024>>>();
    k_hist<<<NB, HNT>>>(dur, N, CH);
    k_scanC<<<1, 1024>>>(N);
    k_blockoff<<<(KBINS * 32 + 255) / 256, 256>>>();
    k_fused<<<NB, FNT>>>(dur, lh, ev, N, CH);
    k_segsum<<<148, 1024, seg_smem>>>(dur, N);
    k_base<<<1, 1024>>>();
    k_mse<<<1184, 256>>>(dur, N);
    k_fin<<<1, 1>>>(out, N);
}

// round 8
// speedup vs baseline: 3.5282x; 1.2027x over previous
#include <cuda_runtime.h>

#define KBINS 10000
#define MAXN  8400000
#define NB    296          // ranking chunks (2 blocks/SM)
#define FNT   256          // fused threads (8 warps)
#define EPT   8            // match rounds per warp turn (256 elems/turn)
#define FTILE (FNT * EPT)  // 2048 elements per block-tile
#define HNT   512
#define SCAN_ITEMS 10      // 1024 * 10 >= KBINS
#define BOT   ((NB + 31) / 32)   // blockoff scan tiles

// ------------------------- static device scratch (no allocs) ----------------
__device__ __align__(16) unsigned int g_expg2[MAXN]; // packed (exp(lh), ev-bit) at desc pos
__device__ __align__(16) int          g_jasc[MAXN];  // jasc[i] = global asc rank of element i
__device__ int   g_H[NB * KBINS];    // per-block histograms
__device__ int   g_O[NB * KBINS];    // per-block per-bin global asc start offsets
__device__ int   g_C[KBINS];         // total counts
__device__ int   g_Sarr[KBINS];      // exclusive prefix S[k]
__device__ int   g_off[KBINS];       // N - 2S - C   (pd = j + off)
__device__ float g_expg_sum[KBINS];
__device__ float g_ev_sum[KBINS];
__device__ float g_base[KBINS];
__device__ float g_totE;
__device__ double g_mse;

// ------------------------- kernels ------------------------------------------
__global__ void k_zero() {
    int i = blockIdx.x * blockDim.x + threadIdx.x;
    if (i < KBINS) g_C[i] = 0;
}

// per-block histogram over contiguous chunk (vectorized loads)
__global__ void k_hist(const int* __restrict__ dur, int N, int CH) {
    __shared__ int sh[KBINS];
    for (int k = threadIdx.x; k < KBINS; k += HNT) sh[k] = 0;
    __syncthreads();
    int b = blockIdx.x;
    int start = b * CH, end = min(start + CH, N);
    int n = end - start;
    int nv = n >> 2;
    const int4* d4 = reinterpret_cast<const int4*>(dur + start);
    for (int g = threadIdx.x; g < nv; g += HNT) {
        int4 k4 = d4[g];
        atomicAdd(&sh[k4.x], 1); atomicAdd(&sh[k4.y], 1);
        atomicAdd(&sh[k4.z], 1); atomicAdd(&sh[k4.w], 1);
    }
    for (int i = start + (nv << 2) + threadIdx.x; i < end; i += HNT)
        atomicAdd(&sh[dur[i]], 1);
    __syncthreads();
    for (int k = threadIdx.x; k < KBINS; k += HNT) {
        int c = sh[k];
        g_H[b * KBINS + k] = c;
        if (c) atomicAdd(&g_C[k], c);
    }
}

// exclusive scan of C -> S; off = N - 2S - C; also zero seg bins (single block)
__global__ void k_scanC(int N) {
    __shared__ int s[1024];
    int tid = threadIdx.x;
    int loc[SCAN_ITEMS];
    int run = 0;
#pragma unroll
    for (int i = 0; i < SCAN_ITEMS; i++) {
        int k = tid * SCAN_ITEMS + i;
        int c = (k < KBINS) ? g_C[k] : 0;
        loc[i] = run;
        run += c;
    }
    s[tid] = run;
    __syncthreads();
    for (int o = 1; o < 1024; o <<= 1) {
        int v = (tid >= o) ? s[tid - o] : 0;
        __syncthreads();
        s[tid] += v;
        __syncthreads();
    }
    int excl = tid ? s[tid - 1] : 0;
#pragma unroll
    for (int i = 0; i < SCAN_ITEMS; i++) {
        int k = tid * SCAN_ITEMS + i;
        if (k < KBINS) {
            int S = excl + loc[i];
            g_Sarr[k] = S;
            g_off[k]  = N - 2 * S - g_C[k];
            g_expg_sum[k] = 0.f;
            g_ev_sum[k]   = 0.f;
        }
    }
}

// O[b][k] = S[k] + sum_{b'<b} H[b'][k]
// Tiled transpose: 32 bins per block staged through padded smem so global
// reads/writes are coalesced; warp-per-bin shfl scan over b in smem.
__global__ void __launch_bounds__(256) k_blockoff() {
    __shared__ int tile[NB * 33];
    int k0 = blockIdx.x * 32;
    // coalesced load: consecutive threads -> consecutive k
    for (int idx = threadIdx.x; idx < NB * 32; idx += 256) {
        int b = idx >> 5, c = idx & 31;
        int k = k0 + c;
        tile[b * 33 + c] = (k < KBINS) ? g_H[b * KBINS + k] : 0;
    }
    __syncthreads();
    int wid = threadIdx.x >> 5, lane = threadIdx.x & 31;
    for (int c = wid; c < 32; c += 8) {
        int k = k0 + c;
        if (k >= KBINS) continue;
        int carry = __shfl_sync(0xffffffffu, (lane == 0) ? g_Sarr[k] : 0, 0);
#pragma unroll
        for (int t = 0; t < BOT; t++) {
            int b = t * 32 + lane;
            int v = (b < NB) ? tile[b * 33 + c] : 0;
            int x = v;
#pragma unroll
            for (int o = 1; o < 32; o <<= 1) {
                int y = __shfl_up_sync(0xffffffffu, x, o);
                if (lane >= o) x += y;
            }
            if (b < NB) tile[b * 33 + c] = carry + x - v;  // exclusive + S
            carry += __shfl_sync(0xffffffffu, x, 31);
        }
    }
    __syncthreads();
    // coalesced store
    for (int idx = threadIdx.x; idx < NB * 32; idx += 256) {
        int b = idx >> 5, c = idx & 31;
        int k = k0 + c;
        if (k < KBINS) g_O[b * KBINS + k] = tile[b * 33 + c];
    }
}

// Fused stable-rank + scatter. Warps hand off a per-block smem ticket so the
// serialized per-key ranking runs with NO block barriers; everything heavy
// (loads, expf) happens outside the critical section.
__global__ void __launch_bounds__(FNT, 2)
k_fused(const int* __restrict__ dur, const float* __restrict__ lh,
        const int* __restrict__ ev, int N, int CH) {
    __shared__ int s_cnt[KBINS + 1];   // running global asc positions (+ sentinel)
    __shared__ int s_flag;
    int tid = threadIdx.x, wid = tid >> 5, lane = tid & 31;
    unsigned lt = (1u << lane) - 1u;
    int b = blockIdx.x;
    for (int k = tid; k < KBINS; k += FNT) s_cnt[k] = g_O[b * KBINS + k];
    if (tid == 0) { s_cnt[KBINS] = 0; s_flag = 0; }
    __syncthreads();

    int start = b * CH, end = min(start + CH, N);
    int ticket = 0;
    for (int t0 = start; t0 < end; t0 += FTILE, ticket += 8) {
        int key[EPT]; unsigned px[EPT]; int idx0 = t0 + wid * (EPT * 32) + lane;
        // ---- prefetch + compute outside critical section ----
#pragma unroll
        for (int m = 0; m < EPT; m++) {
            int i = idx0 + m * 32;
            bool v = (i < end);
            key[m] = v ? dur[i] : KBINS;
            float lhv = v ? lh[i] : 0.f;
            int evv = v ? (ev[i] & 1) : 0;
            px[m] = (__float_as_uint(__expf(lhv)) & 0xFFFFFFFEu) | (unsigned)evv;
        }
        // ---- wait for our turn (sleep to keep LSU free for the active warp) ----
        int target = ticket + wid;
        while (*(volatile int*)&s_flag != target) __nanosleep(40);
        __threadfence_block();
        // ---- serialized ranking (smem only) ----
        int j[EPT];
#pragma unroll
        for (int m = 0; m < EPT; m++) {
            unsigned mask = __match_any_sync(0xffffffffu, key[m]);
            int r = __popc(mask & lt);
            int base = s_cnt[key[m]];
            __syncwarp();
            if (r == 0) s_cnt[key[m]] = base + __popc(mask);
            __syncwarp();
            j[m] = base + r;
        }
        __threadfence_block();
        if (lane == 0) *(volatile int*)&s_flag = target + 1;
        // ---- writes outside critical section ----
#pragma unroll
        for (int m = 0; m < EPT; m++) {
            if (key[m] < KBINS) {
                int i = idx0 + m * 32;
                int pd = j[m] + __ldg(g_off + key[m]);
                g_expg2[pd] = px[m];
                g_jasc[i]   = j[m];
            }
        }
    }
}

// linear segment sums: expg_sum[dur[p]] += exp-part(expg2[p]); ev_sum += bit
__global__ void k_segsum(const int* __restrict__ dur, int N) {
    extern __shared__ char smraw[];
    float* sE = (float*)smraw;
    int*   sV = (int*)(smraw + KBINS * 4);
    for (int k = threadIdx.x; k < KBINS; k += blockDim.x) { sE[k] = 0.f; sV[k] = 0; }
    __syncthreads();
    int stride = gridDim.x * blockDim.x;
    int Nv = N >> 2;
    for (int g = blockIdx.x * blockDim.x + threadIdx.x; g < Nv; g += stride) {
        int p = g * 4;
        int4 k4 = *reinterpret_cast<const int4*>(dur + p);
        uint4 x4 = *reinterpret_cast<const uint4*>(g_expg2 + p);
        atomicAdd(&sE[k4.x], __uint_as_float(x4.x & 0xFFFFFFFEu));
        atomicAdd(&sE[k4.y], __uint_as_float(x4.y & 0xFFFFFFFEu));
        atomicAdd(&sE[k4.z], __uint_as_float(x4.z & 0xFFFFFFFEu));
        atomicAdd(&sE[k4.w], __uint_as_float(x4.w & 0xFFFFFFFEu));
        if (x4.x & 1u) atomicAdd(&sV[k4.x], 1);
        if (x4.y & 1u) atomicAdd(&sV[k4.y], 1);
        if (x4.z & 1u) atomicAdd(&sV[k4.z], 1);
        if (x4.w & 1u) atomicAdd(&sV[k4.w], 1);
    }
    if (blockIdx.x == 0 && threadIdx.x < (N & 3)) {
        int p = (N & ~3) + threadIdx.x;
        int k = dur[p];
        unsigned x = g_expg2[p];
        atomicAdd(&sE[k], __uint_as_float(x & 0xFFFFFFFEu));
        if (x & 1u) atomicAdd(&sV[k], 1);
    }
    __syncthreads();
    for (int k = threadIdx.x; k < KBINS; k += blockDim.x) {
        float a = sE[k]; int c = sV[k];
        if (a != 0.f) atomicAdd(&g_expg_sum[k], a);
        if (c)        atomicAdd(&g_ev_sum[k], (float)c);
    }
}

// base[k] = ev_sum / reverse-cumsum(expg_sum); totE; reset mse
__global__ void k_base() {
    __shared__ float s[1024];
    __shared__ float s2[32];
    int tid = threadIdx.x;
    float loc[SCAN_ITEMS];
    float run = 0.f, evt = 0.f;
#pragma unroll
    for (int i = 0; i < SCAN_ITEMS; i++) {
        int m = tid * SCAN_ITEMS + i;
        int k = KBINS - 1 - m;
        float v = (k >= 0) ? g_expg_sum[k] : 0.f;
        if (k >= 0) evt += g_ev_sum[k];
        run += v;
        loc[i] = run;
    }
    s[tid] = run;
    __syncthreads();
    for (int o = 1; o < 1024; o <<= 1) {
        float v = (tid >= o) ? s[tid - o] : 0.f;
        __syncthreads();
        s[tid] += v;
        __syncthreads();
    }
    float excl = tid ? s[tid - 1] : 0.f;
#pragma unroll
    for (int i = 0; i < SCAN_ITEMS; i++) {
        int m = tid * SCAN_ITEMS + i;
        int k = KBINS - 1 - m;
        if (k >= 0) {
            float risk = excl + loc[i];
            g_base[k] = (risk > 0.f) ? (g_ev_sum[k] / risk) : 0.f;
        }
    }
    for (int o = 16; o; o >>= 1) evt += __shfl_down_sync(0xffffffffu, evt, o);
    if ((tid & 31) == 0) s2[tid >> 5] = evt;
    __syncthreads();
    if (tid < 32) {
        float v = s2[tid];
        for (int o = 16; o; o >>= 1) v += __shfl_down_sync(0xffffffffu, v, o);
        if (tid == 0) { g_totE = v; g_mse = 0.0; }
    }
}

// per original element i: term = (base[dur[i]] * exp-part(expg2[jasc[i]]) - ebit(expg2[i]))^2
__global__ void k_mse(const int* __restrict__ dur, int N) {
    double acc = 0.0;
    int stride = gridDim.x * blockDim.x;
    int Nv = N >> 2;
    for (int g = blockIdx.x * blockDim.x + threadIdx.x; g < Nv; g += stride) {
        int i = g * 4;
        int4  k4 = *reinterpret_cast<const int4*>(dur + i);
        int4  j4 = *reinterpret_cast<const int4*>(g_jasc + i);
        uint4 p4 = *reinterpret_cast<const uint4*>(g_expg2 + i);
        unsigned q0 = __ldg(g_expg2 + j4.x), q1 = __ldg(g_expg2 + j4.y);
        unsigned q2 = __ldg(g_expg2 + j4.z), q3 = __ldg(g_expg2 + j4.w);
        float t0 = g_base[k4.x] * __uint_as_float(q0 & 0xFFFFFFFEu) - (float)(p4.x & 1u);
        float t1 = g_base[k4.y] * __uint_as_float(q1 & 0xFFFFFFFEu) - (float)(p4.y & 1u);
        float t2 = g_base[k4.z] * __uint_as_float(q2 & 0xFFFFFFFEu) - (float)(p4.z & 1u);
        float t3 = g_base[k4.w] * __uint_as_float(q3 & 0xFFFFFFFEu) - (float)(p4.w & 1u);
        acc += (double)(t0 * t0 + t1 * t1 + t2 * t2 + t3 * t3);
    }
    if (blockIdx.x == 0 && threadIdx.x < (N & 3)) {
        int i = (N & ~3) + threadIdx.x;
        unsigned q = g_expg2[g_jasc[i]];
        float t = g_base[dur[i]] * __uint_as_float(q & 0xFFFFFFFEu)
                - (float)(g_expg2[i] & 1u);
        acc += (double)(t * t);
    }
    __shared__ double sd[32];
    for (int o = 16; o; o >>= 1) acc += __shfl_down_sync(0xffffffffu, acc, o);
    if ((threadIdx.x & 31) == 0) sd[threadIdx.x >> 5] = acc;
    __syncthreads();
    if (threadIdx.x < 32) {
        int nw = blockDim.x >> 5;
        double v = (threadIdx.x < nw) ? sd[threadIdx.x] : 0.0;
        for (int o = 16; o; o >>= 1) v += __shfl_down_sync(0xffffffffu, v, o);
        if (threadIdx.x == 0) atomicAdd(&g_mse, v);
    }
}

__global__ void k_fin(float* out, int N) {
    out[0] = (g_totE == 0.f) ? 0.f : (float)(g_mse / (double)N);
}

// ------------------------- host launcher ------------------------------------
extern "C" void kernel_launch(void* const* d_in, const int* in_sizes, int n_in,
                              void* d_out, int out_size) {
    const float* lh  = (const float*)d_in[0];
    const int*   dur = (const int*)d_in[1];
    const int*   ev  = (const int*)d_in[2];
    int N = in_sizes[0];
    float* out = (float*)d_out;
    int CH = (N + NB - 1) / NB;

    size_t seg_smem = (size_t)KBINS * 8;
    cudaFuncSetAttribute(k_segsum, cudaFuncAttributeMaxDynamicSharedMemorySize,
                         (int)seg_smem);

    k_zero<<<(KBINS + 1023) / 1024, 1024>>>();
    k_hist<<<NB, HNT>>>(dur, N, CH);
    k_scanC<<<1, 1024>>>(N);
    k_blockoff<<<(KBINS + 31) / 32, 256>>>();
    k_fused<<<NB, FNT>>>(dur, lh, ev, N, CH);
    k_segsum<<<148, 1024, seg_smem>>>(dur, N);
    k_base<<<1, 1024>>>();
    k_mse<<<1184, 256>>>(dur, N);
    k_fin<<<1, 1>>>(out, N);
}